// round 1
// baseline (speedup 1.0000x reference)
#include <cuda_runtime.h>
#include <math.h>

#define NN 50000
#define EE 800000
#define ETOT (EE + NN)      // edges + self loops
#define FF 128              // HEADS*HID = F_IN
#define HH 4
#define CC 32
#define NC 8

// ---- scratch (device globals; no allocation allowed) ----
__device__ float g_ht[NN * FF];     // transformed features (layer in-flight)
__device__ float g_feat[NN * FF];   // layer output -> next layer input
__device__ float g_out[NN * FF];    // aggregation accumulator
__device__ float g_as[NN * HH];
__device__ float g_ad[NN * HH];
__device__ float g_mx[NN * HH];
__device__ float g_sm[NN * HH];
__device__ float g_e[(size_t)ETOT * HH];   // edge logits -> exp values

__device__ __forceinline__ void atomicMaxF(float* addr, float v) {
    // standard signed/unsigned trick; correct for mixed signs with -inf init
    if (v >= 0.0f) atomicMax((int*)addr, __float_as_int(v));
    else           atomicMin((unsigned int*)addr, __float_as_uint(v));
}

// ---- init accumulators ----
__global__ void k_init(int nh, int nf) {
    int i = blockIdx.x * blockDim.x + threadIdx.x;
    if (i < nf) g_out[i] = 0.0f;
    if (i < nh) { g_mx[i] = -INFINITY; g_sm[i] = 0.0f; }
}

// ---- node GEMM: 128 -> 128, one block per node ----
__global__ void k_gemm128(const float* __restrict__ X, const float* __restrict__ W) {
    __shared__ float xs[FF];
    int n = blockIdx.x;
    int t = threadIdx.x;
    xs[t] = X[n * FF + t];
    __syncthreads();
    float acc = 0.0f;
#pragma unroll
    for (int k = 0; k < FF; k++) acc += xs[k] * W[k * FF + t];
    g_ht[n * FF + t] = acc;
}

// ---- node GEMM: 128 -> 8 ----
__global__ void k_gemm8(const float* __restrict__ W) {
    int i = blockIdx.x * blockDim.x + threadIdx.x;
    if (i >= NN * NC) return;
    int n = i / NC, m = i - n * NC;
    const float* x = &g_feat[n * FF];
    float acc = 0.0f;
#pragma unroll 8
    for (int k = 0; k < FF; k++) acc += x[k] * W[k * NC + m];
    g_ht[i] = acc;
}

// ---- attention coefficients, 4 heads x 32 channels (warp reduce per head) ----
__global__ void k_attn(const float* __restrict__ as, const float* __restrict__ ad) {
    int n = blockIdx.x, t = threadIdx.x;
    float h = g_ht[n * FF + t];
    float ps = h * as[t];
    float pd = h * ad[t];
#pragma unroll
    for (int off = 16; off > 0; off >>= 1) {
        ps += __shfl_down_sync(0xffffffffu, ps, off);
        pd += __shfl_down_sync(0xffffffffu, pd, off);
    }
    if ((t & 31) == 0) {
        g_as[n * HH + (t >> 5)] = ps;
        g_ad[n * HH + (t >> 5)] = pd;
    }
}

// ---- attention coefficients layer 2 (1 head, 8 channels) ----
__global__ void k_attn2(const float* __restrict__ as, const float* __restrict__ ad) {
    int n = blockIdx.x * blockDim.x + threadIdx.x;
    if (n >= NN) return;
    float ps = 0.0f, pd = 0.0f;
#pragma unroll
    for (int j = 0; j < NC; j++) {
        float h = g_ht[n * NC + j];
        ps += h * as[j];
        pd += h * ad[j];
    }
    g_as[n] = ps;
    g_ad[n] = pd;
}

// ---- edge pass 1: leaky-relu logits + segment max ----
template <int H>
__global__ void k_elog(const int* __restrict__ ei) {
    int i = blockIdx.x * blockDim.x + threadIdx.x;
    if (i >= ETOT * H) return;
    int e = i / H, h = i - e * H;
    int s, d;
    if (e < EE) { s = ei[e]; d = ei[EE + e]; } else { s = d = e - EE; }
    float v = g_as[s * H + h] + g_ad[d * H + h];
    v = v > 0.0f ? v : 0.2f * v;
    g_e[i] = v;
    atomicMaxF(&g_mx[d * H + h], v);
}

// ---- edge pass 2: exp + segment sum ----
template <int H>
__global__ void k_eexp(const int* __restrict__ ei) {
    int i = blockIdx.x * blockDim.x + threadIdx.x;
    if (i >= ETOT * H) return;
    int e = i / H, h = i - e * H;
    int d;
    if (e < EE) { d = ei[EE + e]; } else { d = e - EE; }
    float ex = expf(g_e[i] - g_mx[d * H + h]);
    g_e[i] = ex;
    atomicAdd(&g_sm[d * H + h], ex);
}

// ---- edge pass 3: weighted aggregation (the heavy one) ----
template <int H, int C>
__global__ void k_eagg(const int* __restrict__ ei) {
    const int HC = H * C;
    int i = blockIdx.x * blockDim.x + threadIdx.x;
    if (i >= ETOT * HC) return;
    int e = i / HC;
    int c = i - e * HC;
    int h = c / C;
    int s, d;
    if (e < EE) { s = ei[e]; d = ei[EE + e]; } else { s = d = e - EE; }
    float alpha = g_e[e * H + h] / (g_sm[d * H + h] + 1e-16f);
    atomicAdd(&g_out[d * HC + c], g_ht[s * HC + c] * alpha);
}

// ---- bias + BN(eval) + ELU ----
__global__ void k_post(const float* __restrict__ b, const float* __restrict__ g,
                       const float* __restrict__ bb, const float* __restrict__ rm,
                       const float* __restrict__ rv) {
    int i = blockIdx.x * blockDim.x + threadIdx.x;
    if (i >= NN * FF) return;
    int c = i & (FF - 1);
    float v = g_out[i] + b[c];
    v = (v - rm[c]) * rsqrtf(rv[c] + 1e-5f) * g[c] + bb[c];
    g_feat[i] = v > 0.0f ? v : expm1f(v);
}

// ---- bias + log_softmax over 8 classes ----
__global__ void k_final(const float* __restrict__ b2, float* __restrict__ out) {
    int n = blockIdx.x * blockDim.x + threadIdx.x;
    if (n >= NN) return;
    float v[NC];
    float mx = -INFINITY;
#pragma unroll
    for (int j = 0; j < NC; j++) {
        v[j] = g_out[n * NC + j] + b2[j];
        mx = fmaxf(mx, v[j]);
    }
    float s = 0.0f;
#pragma unroll
    for (int j = 0; j < NC; j++) s += expf(v[j] - mx);
    float ls = logf(s) + mx;
#pragma unroll
    for (int j = 0; j < NC; j++) out[n * NC + j] = v[j] - ls;
}

extern "C" void kernel_launch(void* const* d_in, const int* in_sizes, int n_in,
                              void* d_out, int out_size) {
    const float* x   = (const float*)d_in[0];
    const int*   ei  = (const int*)d_in[1];
    const float* W0  = (const float*)d_in[2];
    const float* as0 = (const float*)d_in[3];
    const float* ad0 = (const float*)d_in[4];
    const float* b0  = (const float*)d_in[5];
    const float* g0  = (const float*)d_in[6];
    const float* bb0 = (const float*)d_in[7];
    const float* rm0 = (const float*)d_in[8];
    const float* rv0 = (const float*)d_in[9];
    const float* W1  = (const float*)d_in[10];
    const float* as1 = (const float*)d_in[11];
    const float* ad1 = (const float*)d_in[12];
    const float* b1  = (const float*)d_in[13];
    const float* g1  = (const float*)d_in[14];
    const float* bb1 = (const float*)d_in[15];
    const float* rm1 = (const float*)d_in[16];
    const float* rv1 = (const float*)d_in[17];
    const float* W2  = (const float*)d_in[18];
    const float* as2 = (const float*)d_in[19];
    const float* ad2 = (const float*)d_in[20];
    const float* b2  = (const float*)d_in[21];
    float* out = (float*)d_out;

    float* feat_ptr = nullptr;
    cudaGetSymbolAddress((void**)&feat_ptr, g_feat);

    const int TB = 256;
    const int nf = NN * FF;
    const int nh4 = NN * HH;

    // ======== layer 0 (128 -> 4x32, concat) ========
    k_init<<<(nf + TB - 1) / TB, TB>>>(nh4, nf);
    k_gemm128<<<NN, FF>>>(x, W0);
    k_attn<<<NN, FF>>>(as0, ad0);
    k_elog<HH><<<(ETOT * HH + TB - 1) / TB, TB>>>(ei);
    k_eexp<HH><<<(ETOT * HH + TB - 1) / TB, TB>>>(ei);
    k_eagg<HH, CC><<<(ETOT * FF + TB - 1) / TB, TB>>>(ei);
    k_post<<<(nf + TB - 1) / TB, TB>>>(b0, g0, bb0, rm0, rv0);

    // ======== layer 1 (128 -> 4x32, concat) ========
    k_init<<<(nf + TB - 1) / TB, TB>>>(nh4, nf);
    k_gemm128<<<NN, FF>>>(feat_ptr, W1);
    k_attn<<<NN, FF>>>(as1, ad1);
    k_elog<HH><<<(ETOT * HH + TB - 1) / TB, TB>>>(ei);
    k_eexp<HH><<<(ETOT * HH + TB - 1) / TB, TB>>>(ei);
    k_eagg<HH, CC><<<(ETOT * FF + TB - 1) / TB, TB>>>(ei);
    k_post<<<(nf + TB - 1) / TB, TB>>>(b1, g1, bb1, rm1, rv1);

    // ======== layer 2 (128 -> 8, 1 head, mean==identity) ========
    k_init<<<(NN * NC + TB - 1) / TB, TB>>>(NN, NN * NC);
    k_gemm8<<<(NN * NC + TB - 1) / TB, TB>>>(W2);
    k_attn2<<<(NN + TB - 1) / TB, TB>>>(as2, ad2);
    k_elog<1><<<(ETOT + TB - 1) / TB, TB>>>(ei);
    k_eexp<1><<<(ETOT + TB - 1) / TB, TB>>>(ei);
    k_eagg<1, NC><<<(ETOT * NC + TB - 1) / TB, TB>>>(ei);
    k_final<<<(NN + TB - 1) / TB, TB>>>(b2, out);
}

// round 2
// speedup vs baseline: 2.3366x; 2.3366x over previous
#include <cuda_runtime.h>
#include <math.h>

#define NN 50000
#define EE 800000
#define ETOT (EE + NN)      // edges + self loops
#define FF 128              // HEADS*HID = F_IN
#define HH 4
#define CC 32
#define NC 8

// ---- scratch (device globals; no allocation allowed) ----
__device__ __align__(16) float g_ht[NN * FF];     // transformed features
__device__ __align__(16) float g_feat[NN * FF];   // layer output -> next input
__device__ __align__(16) float g_out[NN * FF];    // aggregation accumulator
__device__ __align__(16) float g_as[NN * HH];
__device__ __align__(16) float g_ad[NN * HH];
__device__ __align__(16) float g_sm[NN * HH];
__device__ __align__(16) float g_e[(size_t)ETOT * HH];   // edge exp values
__device__ __align__(16) int2  g_ed[ETOT];               // packed (src,dst)

__device__ __forceinline__ void redAdd4(float* addr, float4 v) {
    asm volatile("red.global.add.v4.f32 [%0], {%1,%2,%3,%4};"
                 :: "l"(addr), "f"(v.x), "f"(v.y), "f"(v.z), "f"(v.w)
                 : "memory");
}

// ---- pack edge list (+ implicit self loops) once per call ----
__global__ void k_prep(const int* __restrict__ ei) {
    int e = blockIdx.x * blockDim.x + threadIdx.x;
    if (e >= ETOT) return;
    int2 sd;
    if (e < EE) { sd.x = ei[e]; sd.y = ei[EE + e]; }
    else        { sd.x = sd.y = e - EE; }
    g_ed[e] = sd;
}

// ---- zero accumulators (float4 for g_out) ----
__global__ void k_init(int nf4, int nh) {
    int i = blockIdx.x * blockDim.x + threadIdx.x;
    if (i < nf4) ((float4*)g_out)[i] = make_float4(0.f, 0.f, 0.f, 0.f);
    if (i < nh)  g_sm[i] = 0.0f;
}

// ---- node GEMM 128->128: block = 128 thr = 4 warps, 4 nodes/warp, 16 nodes/block
__global__ __launch_bounds__(128) void k_gemm128(const float* __restrict__ X,
                                                 const float* __restrict__ W) {
    __shared__ float xs[16][FF];
    int warp = threadIdx.x >> 5, lane = threadIdx.x & 31;
    int nb = blockIdx.x * 16;
    for (int i = threadIdx.x; i < 16 * FF; i += 128)
        xs[i >> 7][i & 127] = X[nb * FF + i];
    __syncthreads();
    float4 acc0 = make_float4(0,0,0,0), acc1 = acc0, acc2 = acc0, acc3 = acc0;
    const float4* W4 = (const float4*)W;
    int n0 = warp * 4;
#pragma unroll 4
    for (int k = 0; k < FF; k++) {
        float4 w = W4[k * 32 + lane];
        float x0 = xs[n0 + 0][k], x1 = xs[n0 + 1][k];
        float x2 = xs[n0 + 2][k], x3 = xs[n0 + 3][k];
        acc0.x += x0 * w.x; acc0.y += x0 * w.y; acc0.z += x0 * w.z; acc0.w += x0 * w.w;
        acc1.x += x1 * w.x; acc1.y += x1 * w.y; acc1.z += x1 * w.z; acc1.w += x1 * w.w;
        acc2.x += x2 * w.x; acc2.y += x2 * w.y; acc2.z += x2 * w.z; acc2.w += x2 * w.w;
        acc3.x += x3 * w.x; acc3.y += x3 * w.y; acc3.z += x3 * w.z; acc3.w += x3 * w.w;
    }
    float4* O4 = (float4*)g_ht;
    O4[(nb + n0 + 0) * 32 + lane] = acc0;
    O4[(nb + n0 + 1) * 32 + lane] = acc1;
    O4[(nb + n0 + 2) * 32 + lane] = acc2;
    O4[(nb + n0 + 3) * 32 + lane] = acc3;
}

// ---- node GEMM: 128 -> 8 ----
__global__ void k_gemm8(const float* __restrict__ W) {
    int i = blockIdx.x * blockDim.x + threadIdx.x;
    if (i >= NN * NC) return;
    int n = i / NC, m = i - n * NC;
    const float* x = &g_feat[n * FF];
    float acc = 0.0f;
#pragma unroll 8
    for (int k = 0; k < FF; k++) acc += x[k] * W[k * NC + m];
    g_ht[i] = acc;
}

// ---- attention coefficients, 4 heads x 32 channels ----
__global__ void k_attn(const float* __restrict__ as, const float* __restrict__ ad) {
    int n = blockIdx.x, t = threadIdx.x;
    float h = g_ht[n * FF + t];
    float ps = h * as[t];
    float pd = h * ad[t];
#pragma unroll
    for (int off = 16; off > 0; off >>= 1) {
        ps += __shfl_down_sync(0xffffffffu, ps, off);
        pd += __shfl_down_sync(0xffffffffu, pd, off);
    }
    if ((t & 31) == 0) {
        g_as[n * HH + (t >> 5)] = ps;
        g_ad[n * HH + (t >> 5)] = pd;
    }
}

// ---- attention coefficients layer 2 (1 head, 8 channels) ----
__global__ void k_attn2(const float* __restrict__ as, const float* __restrict__ ad) {
    int n = blockIdx.x * blockDim.x + threadIdx.x;
    if (n >= NN) return;
    float ps = 0.0f, pd = 0.0f;
#pragma unroll
    for (int j = 0; j < NC; j++) {
        float h = g_ht[n * NC + j];
        ps += h * as[j];
        pd += h * ad[j];
    }
    g_as[n] = ps;
    g_ad[n] = pd;
}

// ---- fused edge softmax numerator pass: leaky-relu + exp + segment-sum (H=4)
__global__ void k_eedge4() {
    int e = blockIdx.x * blockDim.x + threadIdx.x;
    if (e >= ETOT) return;
    int2 sd = g_ed[e];
    float4 a = ((const float4*)g_as)[sd.x];
    float4 b = ((const float4*)g_ad)[sd.y];
    float4 v;
    v.x = a.x + b.x; v.y = a.y + b.y; v.z = a.z + b.z; v.w = a.w + b.w;
    v.x = v.x > 0.f ? v.x : 0.2f * v.x;
    v.y = v.y > 0.f ? v.y : 0.2f * v.y;
    v.z = v.z > 0.f ? v.z : 0.2f * v.z;
    v.w = v.w > 0.f ? v.w : 0.2f * v.w;
    float4 ex;
    ex.x = __expf(v.x) ; ex.x = expf(v.x);
    ex.y = expf(v.y); ex.z = expf(v.z); ex.w = expf(v.w);
    ((float4*)g_e)[e] = ex;
    redAdd4(&g_sm[sd.y * 4], ex);
}

// ---- same for H=1 (layer 2) ----
__global__ void k_eedge1() {
    int e = blockIdx.x * blockDim.x + threadIdx.x;
    if (e >= ETOT) return;
    int2 sd = g_ed[e];
    float v = g_as[sd.x] + g_ad[sd.y];
    v = v > 0.f ? v : 0.2f * v;
    float ex = expf(v);
    g_e[e] = ex;
    atomicAdd(&g_sm[sd.y], ex);
}

// ---- weighted aggregation, H=4 C=32: thread = (edge, 4-channel group) ----
__global__ __launch_bounds__(256) void k_eagg4() {
    int i = blockIdx.x * blockDim.x + threadIdx.x;
    if (i >= ETOT * 32) return;
    int e = i >> 5;
    int q = i & 31;           // float4 group 0..31
    int h = q >> 3;           // head
    int2 sd = g_ed[e];
    float alpha = g_e[e * 4 + h] / (g_sm[sd.y * 4 + h] + 1e-16f);
    float4 hv = ((const float4*)g_ht)[sd.x * 32 + q];
    hv.x *= alpha; hv.y *= alpha; hv.z *= alpha; hv.w *= alpha;
    redAdd4(&g_out[(sd.y * 32 + q) * 4], hv);
}

// ---- weighted aggregation, H=1 C=8: thread = (edge, 4-channel group) ----
__global__ __launch_bounds__(256) void k_eagg1() {
    int i = blockIdx.x * blockDim.x + threadIdx.x;
    if (i >= ETOT * 2) return;
    int e = i >> 1;
    int q = i & 1;
    int2 sd = g_ed[e];
    float alpha = g_e[e] / (g_sm[sd.y] + 1e-16f);
    float4 hv = ((const float4*)g_ht)[sd.x * 2 + q];
    hv.x *= alpha; hv.y *= alpha; hv.z *= alpha; hv.w *= alpha;
    redAdd4(&g_out[(sd.y * 2 + q) * 4], hv);
}

// ---- bias + BN(eval) + ELU (float4) ----
__global__ void k_post(const float* __restrict__ b, const float* __restrict__ g,
                       const float* __restrict__ bb, const float* __restrict__ rm,
                       const float* __restrict__ rv) {
    int i = blockIdx.x * blockDim.x + threadIdx.x;
    if (i >= NN * 32) return;
    int c = i & 31;
    float4 v = ((const float4*)g_out)[i];
    float4 B = ((const float4*)b)[c],  G = ((const float4*)g)[c];
    float4 BB = ((const float4*)bb)[c], RM = ((const float4*)rm)[c];
    float4 RV = ((const float4*)rv)[c];
    v.x = (v.x + B.x - RM.x) * rsqrtf(RV.x + 1e-5f) * G.x + BB.x;
    v.y = (v.y + B.y - RM.y) * rsqrtf(RV.y + 1e-5f) * G.y + BB.y;
    v.z = (v.z + B.z - RM.z) * rsqrtf(RV.z + 1e-5f) * G.z + BB.z;
    v.w = (v.w + B.w - RM.w) * rsqrtf(RV.w + 1e-5f) * G.w + BB.w;
    v.x = v.x > 0.f ? v.x : expm1f(v.x);
    v.y = v.y > 0.f ? v.y : expm1f(v.y);
    v.z = v.z > 0.f ? v.z : expm1f(v.z);
    v.w = v.w > 0.f ? v.w : expm1f(v.w);
    ((float4*)g_feat)[i] = v;
}

// ---- bias + log_softmax over 8 classes ----
__global__ void k_final(const float* __restrict__ b2, float* __restrict__ out) {
    int n = blockIdx.x * blockDim.x + threadIdx.x;
    if (n >= NN) return;
    float v[NC];
    float mx = -INFINITY;
#pragma unroll
    for (int j = 0; j < NC; j++) {
        v[j] = g_out[n * NC + j] + b2[j];
        mx = fmaxf(mx, v[j]);
    }
    float s = 0.0f;
#pragma unroll
    for (int j = 0; j < NC; j++) s += expf(v[j] - mx);
    float ls = logf(s) + mx;
#pragma unroll
    for (int j = 0; j < NC; j++) out[n * NC + j] = v[j] - ls;
}

extern "C" void kernel_launch(void* const* d_in, const int* in_sizes, int n_in,
                              void* d_out, int out_size) {
    const float* x   = (const float*)d_in[0];
    const int*   ei  = (const int*)d_in[1];
    const float* W0  = (const float*)d_in[2];
    const float* as0 = (const float*)d_in[3];
    const float* ad0 = (const float*)d_in[4];
    const float* b0  = (const float*)d_in[5];
    const float* g0  = (const float*)d_in[6];
    const float* bb0 = (const float*)d_in[7];
    const float* rm0 = (const float*)d_in[8];
    const float* rv0 = (const float*)d_in[9];
    const float* W1  = (const float*)d_in[10];
    const float* as1 = (const float*)d_in[11];
    const float* ad1 = (const float*)d_in[12];
    const float* b1  = (const float*)d_in[13];
    const float* g1  = (const float*)d_in[14];
    const float* bb1 = (const float*)d_in[15];
    const float* rm1 = (const float*)d_in[16];
    const float* rv1 = (const float*)d_in[17];
    const float* W2  = (const float*)d_in[18];
    const float* as2 = (const float*)d_in[19];
    const float* ad2 = (const float*)d_in[20];
    const float* b2  = (const float*)d_in[21];
    float* out = (float*)d_out;

    float* feat_ptr = nullptr;
    cudaGetSymbolAddress((void**)&feat_ptr, g_feat);

    const int TB = 256;
    const int nf4 = NN * FF / 4;
    const int nh4 = NN * HH;

    k_prep<<<(ETOT + TB - 1) / TB, TB>>>(ei);

    // ======== layer 0 ========
    k_init<<<(nf4 + TB - 1) / TB, TB>>>(nf4, nh4);
    k_gemm128<<<NN / 16, 128>>>(x, W0);
    k_attn<<<NN, FF>>>(as0, ad0);
    k_eedge4<<<(ETOT + TB - 1) / TB, TB>>>();
    k_eagg4<<<(ETOT * 32 + TB - 1) / TB, TB>>>();
    k_post<<<(NN * 32 + TB - 1) / TB, TB>>>(b0, g0, bb0, rm0, rv0);

    // ======== layer 1 ========
    k_init<<<(nf4 + TB - 1) / TB, TB>>>(nf4, nh4);
    k_gemm128<<<NN / 16, 128>>>(feat_ptr, W1);
    k_attn<<<NN, FF>>>(as1, ad1);
    k_eedge4<<<(ETOT + TB - 1) / TB, TB>>>();
    k_eagg4<<<(ETOT * 32 + TB - 1) / TB, TB>>>();
    k_post<<<(NN * 32 + TB - 1) / TB, TB>>>(b1, g1, bb1, rm1, rv1);

    // ======== layer 2 (1 head, 8 out) ========
    k_init<<<(NN * NC / 4 + TB - 1) / TB, TB>>>(NN * NC / 4, NN);
    k_gemm8<<<(NN * NC + TB - 1) / TB, TB>>>(W2);
    k_attn2<<<(NN + TB - 1) / TB, TB>>>(as2, ad2);
    k_eedge1<<<(ETOT + TB - 1) / TB, TB>>>();
    k_eagg1<<<(ETOT * 2 + TB - 1) / TB, TB>>>();
    k_final<<<(NN + TB - 1) / TB, TB>>>(b2, out);
}

// round 3
// speedup vs baseline: 3.7453x; 1.6029x over previous
#include <cuda_runtime.h>
#include <math.h>

#define NN 50000
#define EE 800000
#define ETOT (EE + NN)      // edges + self loops
#define FF 128              // HEADS*HID = F_IN
#define HH 4
#define CC 32
#define NC 8

// ---- scratch (device globals; no allocation allowed) ----
__device__ __align__(16) float g_ht[NN * FF];     // transformed features
__device__ __align__(16) float g_feat[NN * FF];   // layer output -> next input
__device__ __align__(16) float g_out[NN * FF];    // aggregation result
__device__ __align__(16) float g_as[NN * HH];
__device__ __align__(16) float g_ad[NN * HH];
__device__ __align__(16) float g_e[(size_t)ETOT * HH];   // edge exp values (CSR order)
__device__ int g_srcp[ETOT];        // src per edge, sorted by dst (CSR)
__device__ int g_rowptr[NN + 1];    // CSR row pointers (by dst)
__device__ int g_deg[NN];
__device__ int g_ofs[NN];           // scatter cursors

// ================= CSR construction =================
__global__ void k_zero() {
    int i = blockIdx.x * blockDim.x + threadIdx.x;
    if (i < NN) g_deg[i] = 0;
}

__global__ void k_deg(const int* __restrict__ ei) {
    int e = blockIdx.x * blockDim.x + threadIdx.x;
    if (e >= ETOT) return;
    int dst = (e < EE) ? ei[EE + e] : e - EE;
    atomicAdd(&g_deg[dst], 1);
}

// single-block hierarchical scan (warp shfl scans + cross-warp), chunked with carry
__global__ void k_scan() {
    __shared__ int wsum[32];
    __shared__ int carryS;
    int tid = threadIdx.x, lane = tid & 31, wid = tid >> 5;
    if (tid == 0) { carryS = 0; g_rowptr[0] = 0; }
    __syncthreads();
    for (int base = 0; base < NN; base += 1024) {
        int i = base + tid;
        int v = (i < NN) ? g_deg[i] : 0;
        // warp inclusive scan
        int x = v;
#pragma unroll
        for (int off = 1; off < 32; off <<= 1) {
            int t = __shfl_up_sync(0xffffffffu, x, off);
            if (lane >= off) x += t;
        }
        if (lane == 31) wsum[wid] = x;
        __syncthreads();
        if (wid == 0) {
            int w = wsum[lane];
#pragma unroll
            for (int off = 1; off < 32; off <<= 1) {
                int t = __shfl_up_sync(0xffffffffu, w, off);
                if (lane >= off) w += t;
            }
            wsum[lane] = w;
        }
        __syncthreads();
        int inc = x + (wid > 0 ? wsum[wid - 1] : 0);
        int carry = carryS;
        __syncthreads();
        if (i < NN) {
            g_rowptr[i + 1] = carry + inc;
            g_ofs[i] = carry + inc - v;
        }
        if (tid == 1023) carryS = carry + inc;
        __syncthreads();
    }
}

__global__ void k_scatter(const int* __restrict__ ei) {
    int e = blockIdx.x * blockDim.x + threadIdx.x;
    if (e >= ETOT) return;
    int src, dst;
    if (e < EE) { src = ei[e]; dst = ei[EE + e]; } else { src = dst = e - EE; }
    int pos = atomicAdd(&g_ofs[dst], 1);
    g_srcp[pos] = src;
}

// ================= fused GEMM (128->128) + attention coefficients =================
// block = 128 thr (4 warps), 16 nodes/block, 4 nodes/warp, 4 cols (float4)/lane
__global__ __launch_bounds__(128) void k_gemm_attn(const float* __restrict__ X,
                                                   const float* __restrict__ W,
                                                   const float* __restrict__ as_,
                                                   const float* __restrict__ ad_) {
    __shared__ __align__(16) float xs[16 * FF];
    int warp = threadIdx.x >> 5, lane = threadIdx.x & 31;
    int nb = blockIdx.x * 16;
    const float4* X4 = (const float4*)(X + (size_t)nb * FF);
    float4* xs4 = (float4*)xs;
    for (int i = threadIdx.x; i < 16 * 32; i += 128) xs4[i] = X4[i];
    __syncthreads();
    float4 acc[4];
#pragma unroll
    for (int j = 0; j < 4; j++) acc[j] = make_float4(0.f, 0.f, 0.f, 0.f);
    const float4* W4 = (const float4*)W;
    int n0 = warp * 4;
#pragma unroll 2
    for (int k4 = 0; k4 < 32; k4++) {
        float4 xv[4];
#pragma unroll
        for (int j = 0; j < 4; j++) xv[j] = xs4[(n0 + j) * 32 + k4];
#pragma unroll
        for (int c = 0; c < 4; c++) {
            float4 w = W4[(k4 * 4 + c) * 32 + lane];
#pragma unroll
            for (int j = 0; j < 4; j++) {
                float xj = ((const float*)&xv[j])[c];
                acc[j].x += xj * w.x; acc[j].y += xj * w.y;
                acc[j].z += xj * w.z; acc[j].w += xj * w.w;
            }
        }
    }
    float4* O4 = (float4*)g_ht;
    float4 as4 = ((const float4*)as_)[lane];
    float4 ad4 = ((const float4*)ad_)[lane];
#pragma unroll
    for (int j = 0; j < 4; j++) {
        O4[(size_t)(nb + n0 + j) * 32 + lane] = acc[j];
        float ps = acc[j].x * as4.x + acc[j].y * as4.y + acc[j].z * as4.z + acc[j].w * as4.w;
        float pd = acc[j].x * ad4.x + acc[j].y * ad4.y + acc[j].z * ad4.z + acc[j].w * ad4.w;
#pragma unroll
        for (int off = 1; off < 8; off <<= 1) {
            ps += __shfl_xor_sync(0xffffffffu, ps, off);
            pd += __shfl_xor_sync(0xffffffffu, pd, off);
        }
        if ((lane & 7) == 0) {
            int h = lane >> 3;
            g_as[(nb + n0 + j) * HH + h] = ps;
            g_ad[(nb + n0 + j) * HH + h] = pd;
        }
    }
}

// ================= CSR aggregation, 4 heads x 32 ch: warp per dst node =================
__global__ __launch_bounds__(256) void k_agg4() {
    int warp = (blockIdx.x * blockDim.x + threadIdx.x) >> 5;
    if (warp >= NN) return;
    int lane = threadIdx.x & 31;
    int start = g_rowptr[warp], end = g_rowptr[warp + 1];
    float4 ad4 = ((const float4*)g_ad)[warp];
    float4 sum = make_float4(0.f, 0.f, 0.f, 0.f);
    // pass A: logits -> exp -> denominator (lanes parallel over edges)
    for (int k = start + lane; k < end; k += 32) {
        int src = g_srcp[k];
        float4 a = ((const float4*)g_as)[src];
        float4 v;
        v.x = a.x + ad4.x; v.y = a.y + ad4.y; v.z = a.z + ad4.z; v.w = a.w + ad4.w;
        v.x = v.x > 0.f ? v.x : 0.2f * v.x;
        v.y = v.y > 0.f ? v.y : 0.2f * v.y;
        v.z = v.z > 0.f ? v.z : 0.2f * v.z;
        v.w = v.w > 0.f ? v.w : 0.2f * v.w;
        float4 ex;
        ex.x = expf(v.x); ex.y = expf(v.y); ex.z = expf(v.z); ex.w = expf(v.w);
        ((float4*)g_e)[k] = ex;
        sum.x += ex.x; sum.y += ex.y; sum.z += ex.z; sum.w += ex.w;
    }
#pragma unroll
    for (int off = 16; off; off >>= 1) {
        sum.x += __shfl_xor_sync(0xffffffffu, sum.x, off);
        sum.y += __shfl_xor_sync(0xffffffffu, sum.y, off);
        sum.z += __shfl_xor_sync(0xffffffffu, sum.z, off);
        sum.w += __shfl_xor_sync(0xffffffffu, sum.w, off);
    }
    int hh = lane >> 3;
    float den = hh == 0 ? sum.x : hh == 1 ? sum.y : hh == 2 ? sum.z : sum.w;
    float inv = 1.f / (den + 1e-16f);
    __syncwarp();
    // pass B: gather + weighted accumulate (lane = channel group)
    float4 acc = make_float4(0.f, 0.f, 0.f, 0.f);
    const float4* ht4 = (const float4*)g_ht;
#pragma unroll 4
    for (int k = start; k < end; k++) {
        int src = g_srcp[k];
        float alpha = g_e[(size_t)k * 4 + hh] * inv;
        float4 hv = ht4[(size_t)src * 32 + lane];
        acc.x += alpha * hv.x; acc.y += alpha * hv.y;
        acc.z += alpha * hv.z; acc.w += alpha * hv.w;
    }
    ((float4*)g_out)[(size_t)warp * 32 + lane] = acc;
}

// ================= layer 2: GEMM 128->8 =================
__global__ void k_gemm8(const float* __restrict__ W) {
    int i = blockIdx.x * blockDim.x + threadIdx.x;
    if (i >= NN * NC) return;
    int n = i / NC, m = i - n * NC;
    const float* x = &g_feat[(size_t)n * FF];
    float acc = 0.0f;
#pragma unroll 8
    for (int k = 0; k < FF; k++) acc += x[k] * W[k * NC + m];
    g_ht[i] = acc;
}

__global__ void k_attn2(const float* __restrict__ as, const float* __restrict__ ad) {
    int n = blockIdx.x * blockDim.x + threadIdx.x;
    if (n >= NN) return;
    float ps = 0.0f, pd = 0.0f;
#pragma unroll
    for (int j = 0; j < NC; j++) {
        float h = g_ht[n * NC + j];
        ps += h * as[j];
        pd += h * ad[j];
    }
    g_as[n] = ps;
    g_ad[n] = pd;
}

// ================= CSR aggregation, 1 head x 8 ch: warp per dst node =================
__global__ __launch_bounds__(256) void k_agg1() {
    int warp = (blockIdx.x * blockDim.x + threadIdx.x) >> 5;
    if (warp >= NN) return;
    int lane = threadIdx.x & 31;
    int start = g_rowptr[warp], end = g_rowptr[warp + 1];
    float adv = g_ad[warp];
    float sum = 0.f;
    for (int k = start + lane; k < end; k += 32) {
        int src = g_srcp[k];
        float v = g_as[src] + adv;
        v = v > 0.f ? v : 0.2f * v;
        float ex = expf(v);
        g_e[k] = ex;
        sum += ex;
    }
#pragma unroll
    for (int off = 16; off; off >>= 1) sum += __shfl_xor_sync(0xffffffffu, sum, off);
    float inv = 1.f / (sum + 1e-16f);
    __syncwarp();
    float4 a0 = make_float4(0.f, 0.f, 0.f, 0.f), a1 = a0;
    const float4* ht4 = (const float4*)g_ht;
    for (int k = start + lane; k < end; k += 32) {
        int src = g_srcp[k];
        float alpha = g_e[k] * inv;
        float4 h0 = ht4[(size_t)src * 2];
        float4 h1 = ht4[(size_t)src * 2 + 1];
        a0.x += alpha * h0.x; a0.y += alpha * h0.y; a0.z += alpha * h0.z; a0.w += alpha * h0.w;
        a1.x += alpha * h1.x; a1.y += alpha * h1.y; a1.z += alpha * h1.z; a1.w += alpha * h1.w;
    }
#pragma unroll
    for (int off = 16; off; off >>= 1) {
        a0.x += __shfl_xor_sync(0xffffffffu, a0.x, off);
        a0.y += __shfl_xor_sync(0xffffffffu, a0.y, off);
        a0.z += __shfl_xor_sync(0xffffffffu, a0.z, off);
        a0.w += __shfl_xor_sync(0xffffffffu, a0.w, off);
        a1.x += __shfl_xor_sync(0xffffffffu, a1.x, off);
        a1.y += __shfl_xor_sync(0xffffffffu, a1.y, off);
        a1.z += __shfl_xor_sync(0xffffffffu, a1.z, off);
        a1.w += __shfl_xor_sync(0xffffffffu, a1.w, off);
    }
    if (lane == 0) {
        ((float4*)g_out)[(size_t)warp * 2] = a0;
        ((float4*)g_out)[(size_t)warp * 2 + 1] = a1;
    }
}

// ================= bias + BN(eval) + ELU =================
__global__ void k_post(const float* __restrict__ b, const float* __restrict__ g,
                       const float* __restrict__ bb, const float* __restrict__ rm,
                       const float* __restrict__ rv) {
    int i = blockIdx.x * blockDim.x + threadIdx.x;
    if (i >= NN * 32) return;
    int c = i & 31;
    float4 v = ((const float4*)g_out)[i];
    float4 B = ((const float4*)b)[c],  G = ((const float4*)g)[c];
    float4 BB = ((const float4*)bb)[c], RM = ((const float4*)rm)[c];
    float4 RV = ((const float4*)rv)[c];
    v.x = (v.x + B.x - RM.x) * rsqrtf(RV.x + 1e-5f) * G.x + BB.x;
    v.y = (v.y + B.y - RM.y) * rsqrtf(RV.y + 1e-5f) * G.y + BB.y;
    v.z = (v.z + B.z - RM.z) * rsqrtf(RV.z + 1e-5f) * G.z + BB.z;
    v.w = (v.w + B.w - RM.w) * rsqrtf(RV.w + 1e-5f) * G.w + BB.w;
    v.x = v.x > 0.f ? v.x : expm1f(v.x);
    v.y = v.y > 0.f ? v.y : expm1f(v.y);
    v.z = v.z > 0.f ? v.z : expm1f(v.z);
    v.w = v.w > 0.f ? v.w : expm1f(v.w);
    ((float4*)g_feat)[i] = v;
}

// ================= bias + log_softmax over 8 classes =================
__global__ void k_final(const float* __restrict__ b2, float* __restrict__ out) {
    int n = blockIdx.x * blockDim.x + threadIdx.x;
    if (n >= NN) return;
    float v[NC];
    float mx = -INFINITY;
#pragma unroll
    for (int j = 0; j < NC; j++) {
        v[j] = g_out[n * NC + j] + b2[j];
        mx = fmaxf(mx, v[j]);
    }
    float s = 0.0f;
#pragma unroll
    for (int j = 0; j < NC; j++) s += expf(v[j] - mx);
    float ls = logf(s) + mx;
#pragma unroll
    for (int j = 0; j < NC; j++) out[n * NC + j] = v[j] - ls;
}

extern "C" void kernel_launch(void* const* d_in, const int* in_sizes, int n_in,
                              void* d_out, int out_size) {
    const float* x   = (const float*)d_in[0];
    const int*   ei  = (const int*)d_in[1];
    const float* W0  = (const float*)d_in[2];
    const float* as0 = (const float*)d_in[3];
    const float* ad0 = (const float*)d_in[4];
    const float* b0  = (const float*)d_in[5];
    const float* g0  = (const float*)d_in[6];
    const float* bb0 = (const float*)d_in[7];
    const float* rm0 = (const float*)d_in[8];
    const float* rv0 = (const float*)d_in[9];
    const float* W1  = (const float*)d_in[10];
    const float* as1 = (const float*)d_in[11];
    const float* ad1 = (const float*)d_in[12];
    const float* b1  = (const float*)d_in[13];
    const float* g1  = (const float*)d_in[14];
    const float* bb1 = (const float*)d_in[15];
    const float* rm1 = (const float*)d_in[16];
    const float* rv1 = (const float*)d_in[17];
    const float* W2  = (const float*)d_in[18];
    const float* as2 = (const float*)d_in[19];
    const float* ad2 = (const float*)d_in[20];
    const float* b2  = (const float*)d_in[21];
    float* out = (float*)d_out;

    float* feat_ptr = nullptr;
    cudaGetSymbolAddress((void**)&feat_ptr, g_feat);

    const int TB = 256;

    // ---- CSR build (per-call, deterministic) ----
    k_zero<<<(NN + TB - 1) / TB, TB>>>();
    k_deg<<<(ETOT + TB - 1) / TB, TB>>>(ei);
    k_scan<<<1, 1024>>>();
    k_scatter<<<(ETOT + TB - 1) / TB, TB>>>(ei);

    // ======== layer 0 ========
    k_gemm_attn<<<NN / 16, 128>>>(x, W0, as0, ad0);
    k_agg4<<<(NN * 32 + TB - 1) / TB, TB>>>();
    k_post<<<(NN * 32 + TB - 1) / TB, TB>>>(b0, g0, bb0, rm0, rv0);

    // ======== layer 1 ========
    k_gemm_attn<<<NN / 16, 128>>>(feat_ptr, W1, as1, ad1);
    k_agg4<<<(NN * 32 + TB - 1) / TB, TB>>>();
    k_post<<<(NN * 32 + TB - 1) / TB, TB>>>(b1, g1, bb1, rm1, rv1);

    // ======== layer 2 (1 head, 8 out) ========
    k_gemm8<<<(NN * NC + TB - 1) / TB, TB>>>(W2);
    k_attn2<<<(NN + TB - 1) / TB, TB>>>(as2, ad2);
    k_agg1<<<(NN * 32 + TB - 1) / TB, TB>>>();
    k_final<<<(NN + TB - 1) / TB, TB>>>(b2, out);
}

// round 4
// speedup vs baseline: 4.0009x; 1.0682x over previous
#include <cuda_runtime.h>
#include <math.h>

#define NN 50000
#define EE 800000
#define ETOT (EE + NN)      // edges + self loops
#define FF 128              // HEADS*HID = F_IN
#define HH 4
#define NC 8

typedef unsigned long long ull;

// ---- scratch (device globals; no allocation allowed) ----
__device__ __align__(16) float g_ht[(size_t)NN * FF];   // transformed features
__device__ __align__(16) float g_feat[(size_t)NN * FF]; // layer output -> next input
__device__ __align__(16) float g_h2[NN * NC];           // layer-2 transformed
__device__ __align__(16) float g_as[NN * HH];
__device__ __align__(16) float g_ad[NN * HH];
__device__ int g_srcp[ETOT];        // src per edge, sorted by dst (CSR)
__device__ int g_rowptr[NN + 1];    // CSR row pointers (by dst)
__device__ int g_deg[NN];
__device__ int g_ofs[NN];           // scatter cursors

// ---- packed f32x2 helpers (Blackwell FFMA2) ----
__device__ __forceinline__ ull fma2(ull a, ull b, ull c) {
    ull d;
    asm("fma.rn.f32x2 %0, %1, %2, %3;" : "=l"(d) : "l"(a), "l"(b), "l"(c));
    return d;
}
__device__ __forceinline__ ull pk2(float v) {
    ull d;
    asm("mov.b64 %0, {%1, %1};" : "=l"(d) : "f"(v));
    return d;
}
__device__ __forceinline__ float2 up2(ull a) {
    float2 r;
    asm("mov.b64 {%0, %1}, %2;" : "=f"(r.x), "=f"(r.y) : "l"(a));
    return r;
}

// ================= CSR construction =================
__global__ void k_zero() {
    int i = blockIdx.x * blockDim.x + threadIdx.x;
    if (i < NN) g_deg[i] = 0;
}

__global__ void k_deg(const int* __restrict__ ei) {
    int e = blockIdx.x * blockDim.x + threadIdx.x;
    if (e >= ETOT) return;
    int dst = (e < EE) ? ei[EE + e] : e - EE;
    atomicAdd(&g_deg[dst], 1);
}

// single-block scan, 4 elements/thread, chunked with carry
__global__ void k_scan() {
    __shared__ int wsum[32];
    __shared__ int carryS;
    int tid = threadIdx.x, lane = tid & 31, wid = tid >> 5;
    if (tid == 0) { carryS = 0; g_rowptr[0] = 0; }
    __syncthreads();
    for (int base = 0; base < NN; base += 4096) {
        int i0 = base + tid * 4;
        int d0 = (i0 + 0 < NN) ? g_deg[i0 + 0] : 0;
        int d1 = (i0 + 1 < NN) ? g_deg[i0 + 1] : 0;
        int d2 = (i0 + 2 < NN) ? g_deg[i0 + 2] : 0;
        int d3 = (i0 + 3 < NN) ? g_deg[i0 + 3] : 0;
        int v = d0 + d1 + d2 + d3;
        int x = v;
#pragma unroll
        for (int off = 1; off < 32; off <<= 1) {
            int t = __shfl_up_sync(0xffffffffu, x, off);
            if (lane >= off) x += t;
        }
        if (lane == 31) wsum[wid] = x;
        __syncthreads();
        if (wid == 0) {
            int w = wsum[lane];
#pragma unroll
            for (int off = 1; off < 32; off <<= 1) {
                int t = __shfl_up_sync(0xffffffffu, w, off);
                if (lane >= off) w += t;
            }
            wsum[lane] = w;
        }
        __syncthreads();
        int inc = x + (wid > 0 ? wsum[wid - 1] : 0);
        int carry = carryS;
        __syncthreads();
        int excl = carry + inc - v;
        int p0 = excl + d0, p1 = p0 + d1, p2 = p1 + d2, p3 = p2 + d3;
        if (i0 + 0 < NN) { g_rowptr[i0 + 1] = p0; g_ofs[i0 + 0] = excl; }
        if (i0 + 1 < NN) { g_rowptr[i0 + 2] = p1; g_ofs[i0 + 1] = p0; }
        if (i0 + 2 < NN) { g_rowptr[i0 + 3] = p2; g_ofs[i0 + 2] = p1; }
        if (i0 + 3 < NN) { g_rowptr[i0 + 4] = p3; g_ofs[i0 + 3] = p2; }
        if (tid == 1023) carryS = carry + inc;
        __syncthreads();
    }
}

__global__ void k_scatter(const int* __restrict__ ei) {
    int e = blockIdx.x * blockDim.x + threadIdx.x;
    if (e >= ETOT) return;
    int src, dst;
    if (e < EE) { src = ei[e]; dst = ei[EE + e]; } else { src = dst = e - EE; }
    int pos = atomicAdd(&g_ofs[dst], 1);
    g_srcp[pos] = src;
}

// ======== fused GEMM (128->128, f32x2 packed) + attention coefficients ========
// block = 128 thr (4 warps), 16 nodes/block, 4 nodes/warp, 4 cols (2xf32x2)/lane
__global__ __launch_bounds__(128) void k_gemm_attn(const float* __restrict__ X,
                                                   const float* __restrict__ W,
                                                   const float* __restrict__ as_,
                                                   const float* __restrict__ ad_) {
    __shared__ __align__(16) float xs[16 * FF];
    int warp = threadIdx.x >> 5, lane = threadIdx.x & 31;
    int nb = blockIdx.x * 16;
    const float4* X4 = (const float4*)(X + (size_t)nb * FF);
    float4* xs4 = (float4*)xs;
    for (int i = threadIdx.x; i < 16 * 32; i += 128) xs4[i] = X4[i];
    __syncthreads();
    ull acc[4][2];
#pragma unroll
    for (int j = 0; j < 4; j++) { acc[j][0] = 0ull; acc[j][1] = 0ull; }
    const ulonglong2* W2 = (const ulonglong2*)W;   // row k: W2[k*32 + lane] = floats [4lane..4lane+3]
    int n0 = warp * 4;
#pragma unroll 4
    for (int k4 = 0; k4 < 32; k4++) {
        float4 xv[4];
#pragma unroll
        for (int j = 0; j < 4; j++) xv[j] = xs4[(n0 + j) * 32 + k4];
#pragma unroll
        for (int c = 0; c < 4; c++) {
            ulonglong2 w = W2[(size_t)(k4 * 4 + c) * 32 + lane];
#pragma unroll
            for (int j = 0; j < 4; j++) {
                float xj = (c == 0) ? xv[j].x : (c == 1) ? xv[j].y : (c == 2) ? xv[j].z : xv[j].w;
                ull xx = pk2(xj);
                acc[j][0] = fma2(w.x, xx, acc[j][0]);
                acc[j][1] = fma2(w.y, xx, acc[j][1]);
            }
        }
    }
    float4* O4 = (float4*)g_ht;
    float4 as4 = ((const float4*)as_)[lane];
    float4 ad4 = ((const float4*)ad_)[lane];
#pragma unroll
    for (int j = 0; j < 4; j++) {
        float2 lo = up2(acc[j][0]), hi = up2(acc[j][1]);
        float4 a = make_float4(lo.x, lo.y, hi.x, hi.y);
        O4[(size_t)(nb + n0 + j) * 32 + lane] = a;
        float ps = a.x * as4.x + a.y * as4.y + a.z * as4.z + a.w * as4.w;
        float pd = a.x * ad4.x + a.y * ad4.y + a.z * ad4.z + a.w * ad4.w;
#pragma unroll
        for (int off = 1; off < 8; off <<= 1) {
            ps += __shfl_xor_sync(0xffffffffu, ps, off);
            pd += __shfl_xor_sync(0xffffffffu, pd, off);
        }
        if ((lane & 7) == 0) {
            int h = lane >> 3;
            g_as[(nb + n0 + j) * HH + h] = ps;
            g_ad[(nb + n0 + j) * HH + h] = pd;
        }
    }
}

// ======== CSR aggregation (single pass) + bias + BN + ELU, 4 heads x 32 ch ========
// warp per dst node; unnormalized accumulate, scale by 1/den at end
__global__ __launch_bounds__(256) void k_agg4(const float* __restrict__ b,
                                              const float* __restrict__ g,
                                              const float* __restrict__ bb,
                                              const float* __restrict__ rm,
                                              const float* __restrict__ rv) {
    __shared__ float4 s_ex[8][32];
    __shared__ int s_src[8][32];
    int wid = threadIdx.x >> 5, lane = threadIdx.x & 31;
    int node = blockIdx.x * 8 + wid;
    int start = g_rowptr[node], end = g_rowptr[node + 1];
    float4 ad4 = ((const float4*)g_ad)[node];
    int hh = lane >> 3;
    float4 acc = make_float4(0.f, 0.f, 0.f, 0.f);
    float4 den = make_float4(0.f, 0.f, 0.f, 0.f);
    const float4* ht4 = (const float4*)g_ht;
    for (int base = start; base < end; base += 32) {
        int k = base + lane;
        float4 ex = make_float4(0.f, 0.f, 0.f, 0.f);
        int src = 0;
        if (k < end) {
            src = g_srcp[k];
            float4 a = ((const float4*)g_as)[src];
            float4 v;
            v.x = a.x + ad4.x; v.y = a.y + ad4.y; v.z = a.z + ad4.z; v.w = a.w + ad4.w;
            v.x = v.x > 0.f ? v.x : 0.2f * v.x;
            v.y = v.y > 0.f ? v.y : 0.2f * v.y;
            v.z = v.z > 0.f ? v.z : 0.2f * v.z;
            v.w = v.w > 0.f ? v.w : 0.2f * v.w;
            ex.x = expf(v.x); ex.y = expf(v.y); ex.z = expf(v.z); ex.w = expf(v.w);
            den.x += ex.x; den.y += ex.y; den.z += ex.z; den.w += ex.w;
        }
        s_src[wid][lane] = src;
        s_ex[wid][lane] = ex;
        __syncwarp();
        int cnt = min(32, end - base);
#pragma unroll 4
        for (int j = 0; j < cnt; j++) {
            int sj = s_src[wid][j];
            float al = ((const float*)&s_ex[wid][j])[hh];
            float4 hv = ht4[(size_t)sj * 32 + lane];
            acc.x += al * hv.x; acc.y += al * hv.y;
            acc.z += al * hv.z; acc.w += al * hv.w;
        }
        __syncwarp();
    }
#pragma unroll
    for (int off = 16; off; off >>= 1) {
        den.x += __shfl_xor_sync(0xffffffffu, den.x, off);
        den.y += __shfl_xor_sync(0xffffffffu, den.y, off);
        den.z += __shfl_xor_sync(0xffffffffu, den.z, off);
        den.w += __shfl_xor_sync(0xffffffffu, den.w, off);
    }
    float d = hh == 0 ? den.x : hh == 1 ? den.y : hh == 2 ? den.z : den.w;
    float inv = 1.f / (d + 1e-16f);
    acc.x *= inv; acc.y *= inv; acc.z *= inv; acc.w *= inv;
    // bias + BN(eval) + ELU epilogue
    float4 B = ((const float4*)b)[lane],  G = ((const float4*)g)[lane];
    float4 BB = ((const float4*)bb)[lane], RM = ((const float4*)rm)[lane];
    float4 RV = ((const float4*)rv)[lane];
    float4 v;
    v.x = (acc.x + B.x - RM.x) * rsqrtf(RV.x + 1e-5f) * G.x + BB.x;
    v.y = (acc.y + B.y - RM.y) * rsqrtf(RV.y + 1e-5f) * G.y + BB.y;
    v.z = (acc.z + B.z - RM.z) * rsqrtf(RV.z + 1e-5f) * G.z + BB.z;
    v.w = (acc.w + B.w - RM.w) * rsqrtf(RV.w + 1e-5f) * G.w + BB.w;
    v.x = v.x > 0.f ? v.x : expm1f(v.x);
    v.y = v.y > 0.f ? v.y : expm1f(v.y);
    v.z = v.z > 0.f ? v.z : expm1f(v.z);
    v.w = v.w > 0.f ? v.w : expm1f(v.w);
    ((float4*)g_feat)[(size_t)node * 32 + lane] = v;
}

// ======== layer 2: fused GEMM 128->8 + attention coefficients (warp/node) ========
__global__ __launch_bounds__(256) void k_gemm8_attn2(const float* __restrict__ W2,
                                                     const float* __restrict__ as2,
                                                     const float* __restrict__ ad2) {
    __shared__ float sWt[NC * FF];   // transposed: [m][k]
    __shared__ float sa[NC], sd[NC];
    for (int i = threadIdx.x; i < FF * NC; i += 256) {
        int k = i >> 3, m = i & 7;
        sWt[m * FF + k] = W2[i];
    }
    if (threadIdx.x < NC) { sa[threadIdx.x] = as2[threadIdx.x]; sd[threadIdx.x] = ad2[threadIdx.x]; }
    __syncthreads();
    int wid = threadIdx.x >> 5, lane = threadIdx.x & 31;
    int node = blockIdx.x * 8 + wid;
    float4 x4 = ((const float4*)g_feat)[(size_t)node * 32 + lane];
    float h[NC];
#pragma unroll
    for (int m = 0; m < NC; m++) {
        float4 w = ((const float4*)(sWt + m * FF))[lane];
        h[m] = x4.x * w.x + x4.y * w.y + x4.z * w.z + x4.w * w.w;
    }
#pragma unroll
    for (int m = 0; m < NC; m++)
#pragma unroll
        for (int off = 16; off; off >>= 1)
            h[m] += __shfl_xor_sync(0xffffffffu, h[m], off);
    if (lane < NC) g_h2[node * NC + lane] = h[lane];
    if (lane == 0) {
        float ps = 0.f, pd = 0.f;
#pragma unroll
        for (int m = 0; m < NC; m++) { ps += h[m] * sa[m]; pd += h[m] * sd[m]; }
        g_as[node] = ps;
        g_ad[node] = pd;
    }
}

// ======== layer 2 CSR aggregation (single pass) + bias + log_softmax ========
__global__ __launch_bounds__(256) void k_agg1_final(const float* __restrict__ b2,
                                                    float* __restrict__ out) {
    int wid = threadIdx.x >> 5, lane = threadIdx.x & 31;
    int node = blockIdx.x * 8 + wid;
    int start = g_rowptr[node], end = g_rowptr[node + 1];
    float adv = g_ad[node];
    float den = 0.f;
    float4 a0 = make_float4(0.f, 0.f, 0.f, 0.f), a1 = a0;
    const float4* h2 = (const float4*)g_h2;
    for (int k = start + lane; k < end; k += 32) {
        int src = g_srcp[k];
        float v = g_as[src] + adv;
        v = v > 0.f ? v : 0.2f * v;
        float ex = expf(v);
        den += ex;
        float4 v0 = h2[(size_t)src * 2];
        float4 v1 = h2[(size_t)src * 2 + 1];
        a0.x += ex * v0.x; a0.y += ex * v0.y; a0.z += ex * v0.z; a0.w += ex * v0.w;
        a1.x += ex * v1.x; a1.y += ex * v1.y; a1.z += ex * v1.z; a1.w += ex * v1.w;
    }
#pragma unroll
    for (int off = 16; off; off >>= 1) {
        den  += __shfl_xor_sync(0xffffffffu, den, off);
        a0.x += __shfl_xor_sync(0xffffffffu, a0.x, off);
        a0.y += __shfl_xor_sync(0xffffffffu, a0.y, off);
        a0.z += __shfl_xor_sync(0xffffffffu, a0.z, off);
        a0.w += __shfl_xor_sync(0xffffffffu, a0.w, off);
        a1.x += __shfl_xor_sync(0xffffffffu, a1.x, off);
        a1.y += __shfl_xor_sync(0xffffffffu, a1.y, off);
        a1.z += __shfl_xor_sync(0xffffffffu, a1.z, off);
        a1.w += __shfl_xor_sync(0xffffffffu, a1.w, off);
    }
    if (lane == 0) {
        float inv = 1.f / (den + 1e-16f);
        float v[NC] = { a0.x * inv + b2[0], a0.y * inv + b2[1],
                        a0.z * inv + b2[2], a0.w * inv + b2[3],
                        a1.x * inv + b2[4], a1.y * inv + b2[5],
                        a1.z * inv + b2[6], a1.w * inv + b2[7] };
        float mx = -INFINITY;
#pragma unroll
        for (int j = 0; j < NC; j++) mx = fmaxf(mx, v[j]);
        float s = 0.f;
#pragma unroll
        for (int j = 0; j < NC; j++) s += expf(v[j] - mx);
        float ls = logf(s) + mx;
#pragma unroll
        for (int j = 0; j < NC; j++) out[node * NC + j] = v[j] - ls;
    }
}

extern "C" void kernel_launch(void* const* d_in, const int* in_sizes, int n_in,
                              void* d_out, int out_size) {
    const float* x   = (const float*)d_in[0];
    const int*   ei  = (const int*)d_in[1];
    const float* W0  = (const float*)d_in[2];
    const float* as0 = (const float*)d_in[3];
    const float* ad0 = (const float*)d_in[4];
    const float* b0  = (const float*)d_in[5];
    const float* g0  = (const float*)d_in[6];
    const float* bb0 = (const float*)d_in[7];
    const float* rm0 = (const float*)d_in[8];
    const float* rv0 = (const float*)d_in[9];
    const float* W1  = (const float*)d_in[10];
    const float* as1 = (const float*)d_in[11];
    const float* ad1 = (const float*)d_in[12];
    const float* b1  = (const float*)d_in[13];
    const float* g1  = (const float*)d_in[14];
    const float* bb1 = (const float*)d_in[15];
    const float* rm1 = (const float*)d_in[16];
    const float* rv1 = (const float*)d_in[17];
    const float* W2  = (const float*)d_in[18];
    const float* as2 = (const float*)d_in[19];
    const float* ad2 = (const float*)d_in[20];
    const float* b2  = (const float*)d_in[21];
    float* out = (float*)d_out;

    float* feat_ptr = nullptr;
    cudaGetSymbolAddress((void**)&feat_ptr, g_feat);

    const int TB = 256;

    // ---- CSR build ----
    k_zero<<<(NN + TB - 1) / TB, TB>>>();
    k_deg<<<(ETOT + TB - 1) / TB, TB>>>(ei);
    k_scan<<<1, 1024>>>();
    k_scatter<<<(ETOT + TB - 1) / TB, TB>>>(ei);

    // ======== layer 0 ========
    k_gemm_attn<<<NN / 16, 128>>>(x, W0, as0, ad0);
    k_agg4<<<NN / 8, TB>>>(b0, g0, bb0, rm0, rv0);

    // ======== layer 1 ========
    k_gemm_attn<<<NN / 16, 128>>>(feat_ptr, W1, as1, ad1);
    k_agg4<<<NN / 8, TB>>>(b1, g1, bb1, rm1, rv1);

    // ======== layer 2 ========
    k_gemm8_attn2<<<NN / 8, TB>>>(W2, as2, ad2);
    k_agg1_final<<<NN / 8, TB>>>(b2, out);
}